// round 8
// baseline (speedup 1.0000x reference)
#include <cuda_runtime.h>
#include <cuda_bf16.h>
#include <cstddef>

// Problem constants
#define BB    16
#define SS    4096
#define DD    1024      // D_IN
#define HH    1024
#define DOUT  1024
#define SPLIT 64
#define ROWS  (SS / SPLIT)   // 64 rows per pass1 block

// GEMV tiling
#define KS    4                    // grid K-splits
#define CHK   (DD / KS)            // 256 k per chunk
#define CF4   (CHK / 4)            // 64 float4 per chunk
#define NPW   2                    // n-rows per warp
#define NPB   (8 * NPW)            // 16 n-rows per block

// Scratch: __device__ globals (no cudaMalloc allowed)
__device__ float g_partial[BB * SPLIT * DD];   // pass1 partials, 4 MB
__device__ float g_m4[4 * BB * DD];            // pass2a partials, 256 KB
__device__ float g_pA[KS * BB * HH];           // gemvA partials, 256 KB
__device__ float g_pB[KS * BB * DOUT];         // gemvB partials, 256 KB
__device__ float g_sink[256 * 256];            // prefetch sink, 256 KB

// ---------------------------------------------------------------------------
// Prefetch: touch W_enc and W_out so they are L2-resident before the gemvs.
// grid 256 x 256. Each thread reads 8 float4 (4 from each W), sums, writes
// to a sink (deterministic; prevents DCE).
// ---------------------------------------------------------------------------
__global__ __launch_bounds__(256) void prefetch_w_kernel(
    const float* __restrict__ W_enc, const float* __restrict__ W_out)
{
    const int tid = blockIdx.x * 256 + threadIdx.x;   // 0..65535
    const float4* A = reinterpret_cast<const float4*>(W_enc);
    const float4* B = reinterpret_cast<const float4*>(W_out);
    float s = 0.f;
    #pragma unroll
    for (int i = 0; i < 4; ++i) {
        float4 a = A[(size_t)i * 65536 + tid];    // covers 4*65536 = 256K f4 = 4 MB
        float4 b = B[(size_t)i * 65536 + tid];
        s += a.x + a.w + b.x + b.w;
    }
    g_sink[tid] = s;
}

// ---------------------------------------------------------------------------
// Pass 1: partial sums over S. grid = (SPLIT, B) = (64,16), block = 256.
// __ldcs: evict-first so the 268MB x-stream does not evict prefetched W.
// ---------------------------------------------------------------------------
__global__ __launch_bounds__(256) void pass1_kernel(const float* __restrict__ x) {
    const int split = blockIdx.x;
    const int b     = blockIdx.y;
    const int t     = threadIdx.x;

    const float4* xp = reinterpret_cast<const float4*>(
        x + ((size_t)b * SS + (size_t)split * ROWS) * DD);

    float4 acc = make_float4(0.f, 0.f, 0.f, 0.f);
    #pragma unroll 16
    for (int r = 0; r < ROWS; ++r) {
        float4 v = __ldcs(&xp[(size_t)r * (DD / 4) + t]);
        acc.x += v.x; acc.y += v.y; acc.z += v.z; acc.w += v.w;
    }

    float4* out = reinterpret_cast<float4*>(
        g_partial + ((size_t)b * SPLIT + split) * DD);
    out[t] = acc;
}

// ---------------------------------------------------------------------------
// Pass 2a: reduce 64 partials in 4 groups of 16 -> g_m4. grid (64,4) x 256.
// ---------------------------------------------------------------------------
__global__ __launch_bounds__(256) void pass2a_kernel() {
    const int idx = blockIdx.x * 256 + threadIdx.x;   // over B*D = 16384
    const int kp  = blockIdx.y;                        // 0..3
    const int b = idx / DD;
    const int d = idx % DD;

    const float* p = g_partial + (size_t)b * SPLIT * DD + (size_t)kp * 16 * DD + d;
    float s = 0.f;
    #pragma unroll
    for (int i = 0; i < 16; ++i) s += p[(size_t)i * DD];

    g_m4[(size_t)kp * (BB * DD) + idx] = s;
}

// ---------------------------------------------------------------------------
// GEMV partial, lanes-along-K (2 f4 per lane) + butterfly reduce.
//   pout[ks][b][n] = sum_{k in chunk ks} v[b][k] * W[n][k]
// grid = (N/16, KS) = (64, 4) = 256 blocks, block = 256 (8 warps).
// W LDGs are issued BEFORE the smem fill so their latency overlaps fill+sync.
// MODE 0: v[b][k] = (sum of 4 g_m4 slices) * 1/SS     (mean finalize fused)
// MODE 1: v[b][k] = (sum of 4 slices) + bias[k]       (prev reduce fused)
// ---------------------------------------------------------------------------
template <int MODE>
__global__ __launch_bounds__(256) void gemv_kernel(
    const float* __restrict__ vsrc,
    const float* __restrict__ bias,
    const float* __restrict__ W,
    float* __restrict__ pout)
{
    __shared__ float4 sV[BB * CF4];   // 16 b x 64 f4 = 16 KB

    const int t    = threadIdx.x;
    const int n0   = blockIdx.x * NPB;
    const int ks   = blockIdx.y;
    const int warp = t >> 5;
    const int lane = t & 31;
    const int n    = n0 + warp * NPW;

    // ---- W loads first (independent of smem) -----------------------------
    const float4* W4 = reinterpret_cast<const float4*>(W);
    const size_t wbase = (size_t)ks * CF4 + lane;
    float4 w0a = W4[(size_t)(n    ) * (DD / 4) + wbase];
    float4 w0b = W4[(size_t)(n    ) * (DD / 4) + wbase + 32];
    float4 w1a = W4[(size_t)(n + 1) * (DD / 4) + wbase];
    float4 w1b = W4[(size_t)(n + 1) * (DD / 4) + wbase + 32];

    // ---- fill v chunk: 1024 float4, 4 per thread, coalesced --------------
    {
        const float4* V4 = reinterpret_cast<const float4*>(vsrc);
        const float4* B4 = reinterpret_cast<const float4*>(bias);
        #pragma unroll
        for (int i = 0; i < 4; ++i) {
            const int id = i * 256 + t;         // 0..1023
            const int b  = id >> 6;
            const int k4 = id & 63;
            const size_t g = (size_t)b * (DD / 4) + (size_t)ks * CF4 + k4;
            float4 v;
            if (MODE == 0) {
                float4 a0 = V4[g];
                float4 a1 = V4[g + (BB * DD) / 4];
                float4 a2 = V4[g + 2 * (BB * DD) / 4];
                float4 a3 = V4[g + 3 * (BB * DD) / 4];
                const float inv = 1.0f / (float)SS;
                v.x = (a0.x + a1.x + a2.x + a3.x) * inv;
                v.y = (a0.y + a1.y + a2.y + a3.y) * inv;
                v.z = (a0.z + a1.z + a2.z + a3.z) * inv;
                v.w = (a0.w + a1.w + a2.w + a3.w) * inv;
            } else {
                float4 a0 = V4[g];
                float4 a1 = V4[g + (BB * HH) / 4];
                float4 a2 = V4[g + 2 * (BB * HH) / 4];
                float4 a3 = V4[g + 3 * (BB * HH) / 4];
                float4 bb = B4[ks * CF4 + k4];
                v.x = a0.x + a1.x + a2.x + a3.x + bb.x;
                v.y = a0.y + a1.y + a2.y + a3.y + bb.y;
                v.z = a0.z + a1.z + a2.z + a3.z + bb.z;
                v.w = a0.w + a1.w + a2.w + a3.w + bb.w;
            }
            sV[id] = v;
        }
    }
    __syncthreads();

    // acc[i], i = n_local*16 + b
    float acc[32];
    #pragma unroll
    for (int i = 0; i < 32; ++i) acc[i] = 0.f;

    #pragma unroll
    for (int b = 0; b < BB; ++b) {
        float4 ma = sV[b * CF4 + lane];
        float4 mb = sV[b * CF4 + lane + 32];
        acc[b]      += ma.x * w0a.x + ma.y * w0a.y + ma.z * w0a.z + ma.w * w0a.w
                     + mb.x * w0b.x + mb.y * w0b.y + mb.z * w0b.z + mb.w * w0b.w;
        acc[16 + b] += ma.x * w1a.x + ma.y * w1a.y + ma.z * w1a.z + ma.w * w1a.w
                     + mb.x * w1b.x + mb.y * w1b.y + mb.z * w1b.z + mb.w * w1b.w;
    }

    // ---- recursive-halving butterfly: 16+8+4+2+1 = 31 shuffles -----------
    #pragma unroll
    for (int step = 0; step < 5; ++step) {
        const int off = 16 >> step;
        const int m   = 32 >> step;
        const bool hi = (lane & off) != 0;
        #pragma unroll
        for (int i = 0; i < 32; ++i) {           // only i < m/2 active
            if (i < m / 2) {
                float tmp  = hi ? acc[i] : acc[i + m / 2];
                float recv = __shfl_xor_sync(0xffffffffu, tmp, off);
                acc[i] = (hi ? acc[i + m / 2] : acc[i]) + recv;
            }
        }
    }

    // lane holds acc[0] for (n_local = lane>>4, b = lane&15)
    const int b_out = lane & 15;
    const int n_out = n + (lane >> 4);
    pout[(size_t)ks * (BB * HH) + (size_t)b_out * HH + n_out] = acc[0];
}

// ---------------------------------------------------------------------------
// Final reduce: out[b][n] = sum of 4 g_pB slices + b_out[n]. 64 x 256.
// ---------------------------------------------------------------------------
__global__ __launch_bounds__(256) void reduce_out_kernel(
    const float* __restrict__ bias, float* __restrict__ out)
{
    const int idx = blockIdx.x * 256 + threadIdx.x;   // over B*DOUT = 16384
    const int nn = idx & (DOUT - 1);
    float s = bias[nn];
    #pragma unroll
    for (int j = 0; j < KS; ++j) s += g_pB[(size_t)j * (BB * DOUT) + idx];
    out[idx] = s;
}

// ---------------------------------------------------------------------------
// Launch. Inputs (metadata order): x, W_enc, b_enc, W_out, b_out.
// ---------------------------------------------------------------------------
extern "C" void kernel_launch(void* const* d_in, const int* in_sizes, int n_in,
                              void* d_out, int out_size)
{
    const float* x     = (const float*)d_in[0];
    const float* W_enc = (const float*)d_in[1];
    const float* b_enc = (const float*)d_in[2];
    const float* W_out = (const float*)d_in[3];
    const float* b_out = (const float*)d_in[4];
    float*       out   = (float*)d_out;

    static float* p_m4 = nullptr;
    static float* p_pA = nullptr;
    if (!p_m4) cudaGetSymbolAddress((void**)&p_m4, g_m4);
    if (!p_pA) cudaGetSymbolAddress((void**)&p_pA, g_pA);

    static float* p_pB = nullptr;
    if (!p_pB) cudaGetSymbolAddress((void**)&p_pB, g_pB);

    // 0) warm L2 with both weight matrices (normal eviction policy)
    prefetch_w_kernel<<<256, 256>>>(W_enc, W_out);
    // 1) partial sums over S (evict-first streaming of x)
    pass1_kernel<<<dim3(SPLIT, BB), 256>>>(x);
    // 2) reduce 64 -> 4 partials
    pass2a_kernel<<<dim3(64, 4), 256>>>();
    // 3) enc partials = mean(x) @ W_enc^T (mean finalize fused into fill)
    gemv_kernel<0><<<dim3(HH / NPB, KS), 256>>>(p_m4, nullptr, W_enc, p_pA);
    // 4) out partials = (enc + b_enc) @ W_out^T (4-way reduce fused into fill)
    gemv_kernel<1><<<dim3(DOUT / NPB, KS), 256>>>(p_pA, b_enc, W_out, p_pB);
    // 5) final reduce + b_out
    reduce_out_kernel<<<64, 256>>>(b_out, out);
}

// round 9
// speedup vs baseline: 1.1019x; 1.1019x over previous
#include <cuda_runtime.h>
#include <cuda_bf16.h>
#include <cstddef>

// Problem constants
#define BB    16
#define SS    4096
#define DD    1024      // D_IN
#define HH    1024
#define DOUT  1024
#define SPLIT 64
#define ROWS  (SS / SPLIT)   // 64 rows per pass1 block

// GEMV tiling
#define KS    4                    // grid K-splits
#define CHK   (DD / KS)            // 256 k per chunk
#define CF4   (CHK / 4)            // 64 float4 per chunk
#define NPW   2                    // n-rows per warp
#define NPB   (8 * NPW)            // 16 n-rows per block

// Scratch: __device__ globals (no cudaMalloc allowed)
__device__ float g_partial[BB * SPLIT * DD];   // pass1 partials, 4 MB
__device__ float g_m4[4 * BB * DD];            // pass2a partials, 256 KB
__device__ float g_m[BB * DD];                 // mean, 64 KB
__device__ float g_enc[BB * HH];               // hidden, 64 KB
__device__ float g_pA[KS * BB * HH];           // gemvA partials, 256 KB
__device__ float g_pB[KS * BB * DOUT];         // gemvB partials, 256 KB
__device__ float g_sink[BB * DD];              // prefetch sink, 64 KB

// ---------------------------------------------------------------------------
// Pass 1: partial sums over S. grid = (SPLIT, B) = (64,16), block = 256.
// __ldcs: evict-first stream of x.
// ---------------------------------------------------------------------------
__global__ __launch_bounds__(256) void pass1_kernel(const float* __restrict__ x) {
    const int split = blockIdx.x;
    const int b     = blockIdx.y;
    const int t     = threadIdx.x;

    const float4* xp = reinterpret_cast<const float4*>(
        x + ((size_t)b * SS + (size_t)split * ROWS) * DD);

    float4 acc = make_float4(0.f, 0.f, 0.f, 0.f);
    #pragma unroll 16
    for (int r = 0; r < ROWS; ++r) {
        float4 v = __ldcs(&xp[(size_t)r * (DD / 4) + t]);
        acc.x += v.x; acc.y += v.y; acc.z += v.z; acc.w += v.w;
    }

    float4* out = reinterpret_cast<float4*>(
        g_partial + ((size_t)b * SPLIT + split) * DD);
    out[t] = acc;
}

// ---------------------------------------------------------------------------
// Pass 2a: reduce 64 partials in 4 groups of 16 -> g_m4. grid (64,5) x 256.
// The 5th y-slice (y==4) streams W_enc into L2 concurrently (post-pass1, so
// nothing evicts it before gemvA).
// ---------------------------------------------------------------------------
__global__ __launch_bounds__(256) void pass2a_kernel(const float* __restrict__ W_enc) {
    const int idx = blockIdx.x * 256 + threadIdx.x;   // 0..16383
    const int kp  = blockIdx.y;

    if (kp == 4) {
        // Prefetch W_enc: 16384 threads x 16 float4 = 4 MB, coalesced
        const float4* A = reinterpret_cast<const float4*>(W_enc);
        float s = 0.f;
        #pragma unroll
        for (int i = 0; i < 16; ++i) {
            float4 a = A[(size_t)i * 16384 + idx];
            s += a.x + a.y + a.z + a.w;
        }
        g_sink[idx] = s;
        return;
    }

    const int b = idx / DD;
    const int d = idx % DD;
    const float* p = g_partial + (size_t)b * SPLIT * DD + (size_t)kp * 16 * DD + d;
    float s = 0.f;
    #pragma unroll
    for (int i = 0; i < 16; ++i) s += p[(size_t)i * DD];

    g_m4[(size_t)kp * (BB * DD) + idx] = s;
}

// ---------------------------------------------------------------------------
// Pass 2b: final 4-way reduce + 1/S scale -> g_m. 64 x 256.
// ---------------------------------------------------------------------------
__global__ __launch_bounds__(256) void pass2b_kernel() {
    const int idx = blockIdx.x * 256 + threadIdx.x;
    float s = g_m4[idx] + g_m4[idx + BB * DD] + g_m4[idx + 2 * BB * DD]
            + g_m4[idx + 3 * BB * DD];
    g_m[idx] = s * (1.0f / (float)SS);
}

// ---------------------------------------------------------------------------
// GEMV partial, lanes-along-K (2 f4 per lane) + butterfly reduce (R6 proven).
//   pout[ks][b][n] = sum_{k in chunk ks} v[b][k] * W[n][k]
// grid = (64, KS [+1]) x 256. If blockIdx.y == KS, the block instead streams
// Wpf (the NEXT layer's weights) into L2, overlapping this gemv's compute.
// ---------------------------------------------------------------------------
__global__ __launch_bounds__(256) void gemv_kernel(
    const float* __restrict__ v,
    const float* __restrict__ W,
    const float* __restrict__ Wpf,
    float* __restrict__ pout)
{
    __shared__ float4 sV[BB * CF4];   // 16 b x 64 f4 = 16 KB

    const int t  = threadIdx.x;
    const int ks = blockIdx.y;

    if (ks == KS) {
        // Prefetch next-layer W: 16384 threads x 16 float4 = 4 MB, coalesced
        const int idx = blockIdx.x * 256 + t;
        const float4* A = reinterpret_cast<const float4*>(Wpf);
        float s = 0.f;
        #pragma unroll
        for (int i = 0; i < 16; ++i) {
            float4 a = A[(size_t)i * 16384 + idx];
            s += a.x + a.y + a.z + a.w;
        }
        g_sink[idx] = s;
        return;
    }

    const int n0 = blockIdx.x * NPB;

    // ---- fill v chunk: 1024 float4, 4 per thread, coalesced --------------
    {
        const float4* V4 = reinterpret_cast<const float4*>(v);
        #pragma unroll
        for (int i = 0; i < 4; ++i) {
            const int id = i * 256 + t;         // 0..1023
            const int b  = id >> 6;
            const int k4 = id & 63;
            sV[id] = V4[(size_t)b * (DD / 4) + (size_t)ks * CF4 + k4];
        }
    }
    __syncthreads();

    const int warp = t >> 5;
    const int lane = t & 31;
    const int n    = n0 + warp * NPW;

    // W: 2 rows x 2 float4 per lane, coalesced across lanes
    const float4* W4 = reinterpret_cast<const float4*>(W);
    const size_t wbase = (size_t)ks * CF4 + lane;
    float4 w0a = W4[(size_t)(n    ) * (DD / 4) + wbase];
    float4 w0b = W4[(size_t)(n    ) * (DD / 4) + wbase + 32];
    float4 w1a = W4[(size_t)(n + 1) * (DD / 4) + wbase];
    float4 w1b = W4[(size_t)(n + 1) * (DD / 4) + wbase + 32];

    // acc[i], i = n_local*16 + b
    float acc[32];
    #pragma unroll
    for (int i = 0; i < 32; ++i) acc[i] = 0.f;

    #pragma unroll
    for (int b = 0; b < BB; ++b) {
        float4 ma = sV[b * CF4 + lane];
        float4 mb = sV[b * CF4 + lane + 32];
        acc[b]      += ma.x * w0a.x + ma.y * w0a.y + ma.z * w0a.z + ma.w * w0a.w
                     + mb.x * w0b.x + mb.y * w0b.y + mb.z * w0b.z + mb.w * w0b.w;
        acc[16 + b] += ma.x * w1a.x + ma.y * w1a.y + ma.z * w1a.z + ma.w * w1a.w
                     + mb.x * w1b.x + mb.y * w1b.y + mb.z * w1b.z + mb.w * w1b.w;
    }

    // ---- recursive-halving butterfly: 16+8+4+2+1 = 31 shuffles -----------
    #pragma unroll
    for (int step = 0; step < 5; ++step) {
        const int off = 16 >> step;
        const int m   = 32 >> step;
        const bool hi = (lane & off) != 0;
        #pragma unroll
        for (int i = 0; i < 32; ++i) {           // only i < m/2 active
            if (i < m / 2) {
                float tmp  = hi ? acc[i] : acc[i + m / 2];
                float recv = __shfl_xor_sync(0xffffffffu, tmp, off);
                acc[i] = (hi ? acc[i + m / 2] : acc[i]) + recv;
            }
        }
    }

    // lane holds acc[0] for (n_local = lane>>4, b = lane&15)
    const int b_out = lane & 15;
    const int n_out = n + (lane >> 4);
    pout[(size_t)ks * (BB * HH) + (size_t)b_out * HH + n_out] = acc[0];
}

// ---------------------------------------------------------------------------
// Reduce KS partial slices + bias. 64 x 256. out[b][n].
// ---------------------------------------------------------------------------
__global__ __launch_bounds__(256) void reduceks_kernel(
    const float* __restrict__ pin,
    const float* __restrict__ bias,
    float* __restrict__ out)
{
    const int idx = blockIdx.x * 256 + threadIdx.x;   // over B*N = 16384
    const int nn = idx & (HH - 1);
    float s = bias[nn];
    #pragma unroll
    for (int j = 0; j < KS; ++j) s += pin[(size_t)j * (BB * HH) + idx];
    out[idx] = s;
}

// ---------------------------------------------------------------------------
// Launch. Inputs (metadata order): x, W_enc, b_enc, W_out, b_out.
// ---------------------------------------------------------------------------
extern "C" void kernel_launch(void* const* d_in, const int* in_sizes, int n_in,
                              void* d_out, int out_size)
{
    const float* x     = (const float*)d_in[0];
    const float* W_enc = (const float*)d_in[1];
    const float* b_enc = (const float*)d_in[2];
    const float* W_out = (const float*)d_in[3];
    const float* b_out = (const float*)d_in[4];
    float*       out   = (float*)d_out;

    static float* p_m   = nullptr;
    static float* p_enc = nullptr;
    static float* p_pA  = nullptr;
    static float* p_pB  = nullptr;
    if (!p_m)   cudaGetSymbolAddress((void**)&p_m,   g_m);
    if (!p_enc) cudaGetSymbolAddress((void**)&p_enc, g_enc);
    if (!p_pA)  cudaGetSymbolAddress((void**)&p_pA,  g_pA);
    if (!p_pB)  cudaGetSymbolAddress((void**)&p_pB,  g_pB);

    // 1) partial sums over S
    pass1_kernel<<<dim3(SPLIT, BB), 256>>>(x);
    // 2) mean level 1 + W_enc L2-prefetch slice (post-pass1, overlapped)
    pass2a_kernel<<<dim3(64, 5), 256>>>(W_enc);
    // 2b) mean finalize
    pass2b_kernel<<<64, 256>>>();
    // 3) enc = m @ W_enc^T (+ W_out L2-prefetch slice, overlapped)
    gemv_kernel<<<dim3(HH / NPB, KS + 1), 256>>>(p_m, W_enc, W_out, p_pA);
    reduceks_kernel<<<64, 256>>>(p_pA, b_enc, p_enc);
    // 4) out = enc @ W_out^T + b_out
    gemv_kernel<<<dim3(DOUT / NPB, KS), 256>>>(p_enc, W_out, nullptr, p_pB);
    reduceks_kernel<<<64, 256>>>(p_pB, b_out, out);
}

// round 10
// speedup vs baseline: 1.1154x; 1.0123x over previous
#include <cuda_runtime.h>
#include <cuda_bf16.h>
#include <cstddef>

// Problem constants
#define BB    16
#define SS    4096
#define DD    1024      // D_IN
#define HH    1024
#define DOUT  1024
#define SPLIT 64
#define ROWS  (SS / SPLIT)   // 64 rows per pass1 block

// GEMV tiling
#define KS    4                    // grid K-splits
#define CHK   (DD / KS)            // 256 k per chunk
#define CF4   (CHK / 4)            // 64 float4 per chunk
#define NPW   2                    // n-rows per warp
#define NPB   (8 * NPW)            // 16 n-rows per block

// Scratch: __device__ globals (no cudaMalloc allowed)
__device__ float g_partial[BB * SPLIT * DD];   // pass1 partials, 4 MB
__device__ float g_m[BB * DD];                 // mean, 64 KB
__device__ float g_enc[BB * HH];               // hidden, 64 KB
__device__ float g_pA[KS * BB * HH];           // gemvA partials, 256 KB
__device__ float g_pB[KS * BB * DOUT];         // gemvB partials, 256 KB

// ---------------------------------------------------------------------------
// Pass 1: partial sums over S. grid = (SPLIT, B) = (64,16), block = 256.
// __ldcs: evict-first stream of x.
// ---------------------------------------------------------------------------
__global__ __launch_bounds__(256) void pass1_kernel(const float* __restrict__ x) {
    const int split = blockIdx.x;
    const int b     = blockIdx.y;
    const int t     = threadIdx.x;

    const float4* xp = reinterpret_cast<const float4*>(
        x + ((size_t)b * SS + (size_t)split * ROWS) * DD);

    float4 acc = make_float4(0.f, 0.f, 0.f, 0.f);
    #pragma unroll 16
    for (int r = 0; r < ROWS; ++r) {
        float4 v = __ldcs(&xp[(size_t)r * (DD / 4) + t]);
        acc.x += v.x; acc.y += v.y; acc.z += v.z; acc.w += v.w;
    }

    float4* out = reinterpret_cast<float4*>(
        g_partial + ((size_t)b * SPLIT + split) * DD);
    out[t] = acc;
}

// ---------------------------------------------------------------------------
// Pass 2: single-level 64-way reduce + 1/S scale -> g_m. 64 blocks x 256.
// Warp reads are coalesced across d for every split i.
// ---------------------------------------------------------------------------
__global__ __launch_bounds__(256) void pass2_kernel() {
    const int idx = blockIdx.x * 256 + threadIdx.x;   // over B*D = 16384
    const int b = idx / DD;
    const int d = idx % DD;

    const float* p = g_partial + (size_t)b * SPLIT * DD + d;
    float s = 0.f;
    #pragma unroll 16
    for (int i = 0; i < SPLIT; ++i) s += p[(size_t)i * DD];

    g_m[idx] = s * (1.0f / (float)SS);
}

// ---------------------------------------------------------------------------
// GEMV partial — NO smem, NO __syncthreads (anti-lockstep version).
//   pout[ks][b][n] = sum_{k in chunk ks} v[b][k] * W[n][k]
// grid = (N/16, KS) = (64, 4) = 256 blocks, block = 256 (8 warps).
// Warp w owns n-rows {n0+2w, n0+2w+1}; lane covers f4 {lane, lane+32} of the
// 256-k chunk. The lane-indexed v operands are loaded straight from gmem
// (coalesced 512B per warp-load, L2-hot: v is only 64 KB shared by all
// blocks). Warps run free — no barrier aligns their stall phases.
// Then the 31-shuffle recursive-halving butterfly; lane L exits holding the
// output with original accumulator index == L (n_local = L>>4, b = L&15).
// ---------------------------------------------------------------------------
__global__ __launch_bounds__(256) void gemv_kernel(
    const float* __restrict__ v,
    const float* __restrict__ W,
    float* __restrict__ pout)
{
    const int t    = threadIdx.x;
    const int warp = t >> 5;
    const int lane = t & 31;
    const int n0   = blockIdx.x * NPB;
    const int ks   = blockIdx.y;
    const int n    = n0 + warp * NPW;

    // W: 2 rows x 2 float4 per lane, coalesced across lanes
    const float4* W4 = reinterpret_cast<const float4*>(W);
    const size_t wbase = (size_t)ks * CF4 + lane;
    float4 w0a = W4[(size_t)(n    ) * (DD / 4) + wbase];
    float4 w0b = W4[(size_t)(n    ) * (DD / 4) + wbase + 32];
    float4 w1a = W4[(size_t)(n + 1) * (DD / 4) + wbase];
    float4 w1b = W4[(size_t)(n + 1) * (DD / 4) + wbase + 32];

    const float4* V4 = reinterpret_cast<const float4*>(v);

    // acc[i], i = n_local*16 + b
    float acc[32];
    #pragma unroll
    for (int i = 0; i < 32; ++i) acc[i] = 0.f;

    #pragma unroll
    for (int b = 0; b < BB; ++b) {
        // lane-indexed v loads, coalesced per warp; unrolled -> high MLP
        float4 ma = V4[(size_t)b * (DD / 4) + wbase];
        float4 mb = V4[(size_t)b * (DD / 4) + wbase + 32];
        acc[b]      += ma.x * w0a.x + ma.y * w0a.y + ma.z * w0a.z + ma.w * w0a.w
                     + mb.x * w0b.x + mb.y * w0b.y + mb.z * w0b.z + mb.w * w0b.w;
        acc[16 + b] += ma.x * w1a.x + ma.y * w1a.y + ma.z * w1a.z + ma.w * w1a.w
                     + mb.x * w1b.x + mb.y * w1b.y + mb.z * w1b.z + mb.w * w1b.w;
    }

    // ---- recursive-halving butterfly: 16+8+4+2+1 = 31 shuffles -----------
    #pragma unroll
    for (int step = 0; step < 5; ++step) {
        const int off = 16 >> step;
        const int m   = 32 >> step;
        const bool hi = (lane & off) != 0;
        #pragma unroll
        for (int i = 0; i < 32; ++i) {           // only i < m/2 active
            if (i < m / 2) {
                float tmp  = hi ? acc[i] : acc[i + m / 2];
                float recv = __shfl_xor_sync(0xffffffffu, tmp, off);
                acc[i] = (hi ? acc[i + m / 2] : acc[i]) + recv;
            }
        }
    }

    // lane holds acc[0] for (n_local = lane>>4, b = lane&15)
    const int b_out = lane & 15;
    const int n_out = n + (lane >> 4);
    pout[(size_t)ks * (BB * HH) + (size_t)b_out * HH + n_out] = acc[0];
}

// ---------------------------------------------------------------------------
// Reduce KS partial slices + bias. 64 x 256. out[b][n].
// ---------------------------------------------------------------------------
__global__ __launch_bounds__(256) void reduceks_kernel(
    const float* __restrict__ pin,
    const float* __restrict__ bias,
    float* __restrict__ out)
{
    const int idx = blockIdx.x * 256 + threadIdx.x;   // over B*N = 16384
    const int nn = idx & (HH - 1);
    float s = bias[nn];
    #pragma unroll
    for (int j = 0; j < KS; ++j) s += pin[(size_t)j * (BB * HH) + idx];
    out[idx] = s;
}

// ---------------------------------------------------------------------------
// Launch. Inputs (metadata order): x, W_enc, b_enc, W_out, b_out.
// ---------------------------------------------------------------------------
extern "C" void kernel_launch(void* const* d_in, const int* in_sizes, int n_in,
                              void* d_out, int out_size)
{
    const float* x     = (const float*)d_in[0];
    const float* W_enc = (const float*)d_in[1];
    const float* b_enc = (const float*)d_in[2];
    const float* W_out = (const float*)d_in[3];
    const float* b_out = (const float*)d_in[4];
    float*       out   = (float*)d_out;

    static float* p_m   = nullptr;
    static float* p_enc = nullptr;
    static float* p_pA  = nullptr;
    static float* p_pB  = nullptr;
    if (!p_m)   cudaGetSymbolAddress((void**)&p_m,   g_m);
    if (!p_enc) cudaGetSymbolAddress((void**)&p_enc, g_enc);
    if (!p_pA)  cudaGetSymbolAddress((void**)&p_pA,  g_pA);
    if (!p_pB)  cudaGetSymbolAddress((void**)&p_pB,  g_pB);

    // 1) partial sums over S
    pass1_kernel<<<dim3(SPLIT, BB), 256>>>(x);
    // 2) mean (single-level 64-way reduce)
    pass2_kernel<<<64, 256>>>();
    // 3) enc = m @ W_enc^T + b_enc
    gemv_kernel<<<dim3(HH / NPB, KS), 256>>>(p_m, W_enc, p_pA);
    reduceks_kernel<<<64, 256>>>(p_pA, b_enc, p_enc);
    // 4) out = enc @ W_out^T + b_out
    gemv_kernel<<<dim3(DOUT / NPB, KS), 256>>>(p_enc, W_out, p_pB);
    reduceks_kernel<<<64, 256>>>(p_pB, b_out, out);
}